// round 15
// baseline (speedup 1.0000x reference)
#include <cuda_runtime.h>
#include <cuda_fp16.h>
#include <cstdint>

// ============================================================
// TopKRouter, warp-specialized HMMA fp16 2-split pipeline v7:
//   logits = x @ W^T + b ; top-2 ; softmax(top2)
// M_CTA=112, grid=147. SMSP-balanced consumer tiles:
//   warps 0-3 (heavy): m16n64, rows 16w      (24 MMAs/kk)
//   warps 4-7 (light): n16 strip, rows 64-111 (18 MMAs/kk)
//   -> every SMSP carries 42 MMAs/kk (vs 48 in R7/R14 binding)
// warps 8-11: producers. 4-stage smem ring.
// ============================================================

#define D_DIM  2048
#define NEXP   64
#define M_CTA  112
#define NCH    32
#define NSTG   4
#define NTHREADS 384

// stage: A-h0 [0,14336) | A-h1 [14336,28672) | W-w0 [28672,36864) | W-w1 [36864,45056)
#define AB       14336
#define WB       8192
#define WOFF     28672
#define STGSZ    45056
#define STG(s)   (1024 + (s) * STGSZ)
#define SMEM_TOTAL (1024 + NSTG * STGSZ)   // 181248
#define LG_OFF   1024
#define LGS      65
#define SW16(row, c) ((row) * 128 + ((((c) ^ ((row) & 7))) << 4))

__device__ __align__(16) __half w0g[NEXP * D_DIM];
__device__ __align__(16) __half w1g[NEXP * D_DIM];

__global__ void wconv(const float* __restrict__ W) {
    int i = blockIdx.x * blockDim.x + threadIdx.x;
    float w = W[i];
    __half h0 = __float2half_rn(w);
    float  r  = w - __half2float(h0);
    w0g[i] = h0;
    w1g[i] = __float2half_rn(r * 2048.0f);
}

// ---------------- asm helpers ----------------
__device__ __forceinline__ uint32_t smem_u32(const void* p) {
    uint32_t a;
    asm("{ .reg .u64 t; cvta.to.shared.u64 t, %1; cvt.u32.u64 %0, t; }"
        : "=r"(a) : "l"(p));
    return a;
}
__device__ __forceinline__ void ldsm4(uint32_t* r, uint32_t addr) {
    asm volatile("ldmatrix.sync.aligned.m8n8.x4.shared.b16 {%0,%1,%2,%3}, [%4];"
                 : "=r"(r[0]), "=r"(r[1]), "=r"(r[2]), "=r"(r[3]) : "r"(addr));
}
__device__ __forceinline__ void mma16816(float* d, const uint32_t* a, const uint32_t* b) {
    asm volatile("mma.sync.aligned.m16n8k16.row.col.f32.f16.f16.f32 "
                 "{%0,%1,%2,%3}, {%4,%5,%6,%7}, {%8,%9}, {%0,%1,%2,%3};"
                 : "+f"(d[0]), "+f"(d[1]), "+f"(d[2]), "+f"(d[3])
                 : "r"(a[0]), "r"(a[1]), "r"(a[2]), "r"(a[3]), "r"(b[0]), "r"(b[1]));
}
__device__ __forceinline__ void cp16(uint32_t saddr, const void* gaddr) {
    asm volatile("cp.async.cg.shared.global [%0], [%1], 16;" :: "r"(saddr), "l"(gaddr));
}
#define MBAR_INIT(a, c) \
    asm volatile("mbarrier.init.shared.b64 [%0], %1;" :: "r"(a), "r"(c) : "memory")
#define MBAR_ARRIVE(a) \
    asm volatile("mbarrier.arrive.release.cta.shared::cta.b64 _, [%0];" :: "r"(a) : "memory")
// .noinc is load-bearing (default raises pend-count -> deadlock)
#define CP_MBAR_ARRIVE(a) \
    asm volatile("cp.async.mbarrier.arrive.noinc.shared.b64 [%0];" :: "r"(a) : "memory")
#define MBAR_WAIT(addr, ph) do { \
    asm volatile("{\n\t.reg .pred P;\n\tWLP_%=:\n\t" \
        "mbarrier.try_wait.parity.acquire.cta.shared::cta.b64 P, [%0], %1, 0x989680;\n\t" \
        "@!P bra WLP_%=;\n\t}" :: "r"(addr), "r"(ph) : "memory"); \
} while (0)
#define STS128(addr, v) \
    asm volatile("st.shared.v4.b32 [%0], {%1,%2,%3,%4};" \
                 :: "r"(addr), "r"((v).x), "r"((v).y), "r"((v).z), "r"((v).w) : "memory")

__device__ __forceinline__ uint32_t cvt2(float u, float v, uint32_t& h1) {
    __half2 a = __float22half2_rn(make_float2(u, v));
    float2 f  = __half22float2(a);
    __half2 r = __float22half2_rn(make_float2(u - f.x, v - f.y));
    h1 = *reinterpret_cast<uint32_t*>(&r);
    return *reinterpret_cast<uint32_t*>(&a);
}

// ---------------- main kernel ----------------
__global__ __launch_bounds__(NTHREADS)
void router_main(const float* __restrict__ x, const float* __restrict__ b,
                 float* __restrict__ out, int n_tokens)
{
    extern __shared__ __align__(1024) char smem[];
    const uint32_t sb = smem_u32(smem);
    const int tid  = threadIdx.x;
    const int lane = tid & 31;
    const int tok0 = blockIdx.x * M_CTA;

    if (tid == 0) {
#pragma unroll
        for (int s = 0; s < NSTG; s++) {
            MBAR_INIT(sb + 512 + s * 16, 256);      // 128 STS-arr + 128 cp-arr
            MBAR_INIT(sb + 512 + s * 16 + 8, 256);  // 256 consumer arrivals
        }
    }
    if (tid < NEXP) reinterpret_cast<float*>(smem)[tid] = b[tid];
    __syncthreads();

    if (tid >= 256) {
        // ================= PRODUCER (warps 8-11, 128 threads) =================
        const int pt   = tid - 256;        // 0..127
        const int wrow = pt & 63;
        const int wsp  = pt >> 6;
        const char* wg = reinterpret_cast<const char*>(wsp ? w1g : w0g)
                         + wrow * (D_DIM * 2);
        const uint32_t wdst = WOFF + wsp * WB;
        uint32_t wsw[8];
#pragma unroll
        for (int c = 0; c < 8; c++) wsw[c] = SW16(wrow, c);

        const bool doX = (pt < M_CTA);
        int xrow = tok0 + pt;
        if (xrow >= n_tokens) xrow = n_tokens - 1;   // clamp (tail CTA)
        const float4* xp = reinterpret_cast<const float4*>(x)
                           + (size_t)xrow * (D_DIM / 4);
        uint32_t asw[8];
#pragma unroll
        for (int q = 0; q < 8; q++) asw[q] = SW16(pt, q);

        float4 xv[16];
        if (doX) {
#pragma unroll
            for (int i = 0; i < 16; i++) xv[i] = xp[i];
        }

        int s = 0, ph = 1;
        for (int ch = 0; ch < NCH; ch++) {
            const uint32_t fullb  = sb + 512 + s * 16;
            const uint32_t emptyb = fullb + 8;
            MBAR_WAIT(emptyb, ph);
            const uint32_t stg = sb + STG(s);

#pragma unroll
            for (int c = 0; c < 8; c++)
                cp16(stg + wdst + wsw[c], wg + ch * 128 + c * 16);

            if (doX) {
#pragma unroll
                for (int q = 0; q < 8; q++) {
                    float4 a = xv[2 * q], c = xv[2 * q + 1];
                    uint4 h0q, h1q;
                    h0q.x = cvt2(a.x, a.y, h1q.x);
                    h0q.y = cvt2(a.z, a.w, h1q.y);
                    h0q.z = cvt2(c.x, c.y, h1q.z);
                    h0q.w = cvt2(c.z, c.w, h1q.w);
                    STS128(stg + asw[q], h0q);
                    STS128(stg + AB + asw[q], h1q);
                }
            }
            CP_MBAR_ARRIVE(fullb);
            MBAR_ARRIVE(fullb);

            if (doX && ch + 1 < NCH) {
#pragma unroll
                for (int i = 0; i < 16; i++) xv[i] = xp[(ch + 1) * 16 + i];
            }
            if (++s == NSTG) { s = 0; ph ^= 1; }
        }
        return;
    }

    // ================= CONSUMERS (warps 0-7) =================
    const int wid = tid >> 5;
    float* lg = reinterpret_cast<float*>(smem + LG_OFF);
    const float S = 4.8828125e-4f;  // 2^-11

    if (wid < 4) {
        // ---- HEAVY: m16n64, rows 16*wid (4 quanta = 24 MMAs/kk) ----
        const int m0 = wid * 16;

        float acc0[8][4], acc1[8][4];
#pragma unroll
        for (int ng = 0; ng < 8; ng++)
#pragma unroll
            for (int q = 0; q < 4; q++) { acc0[ng][q] = 0.f; acc1[ng][q] = 0.f; }

        const int rowA  = m0 + (lane & 15);
        const int cAoff = lane >> 4;
        const int rowBb = (lane & 7) + ((lane >> 4) << 3);
        const int cBoff = (lane >> 3) & 1;

        int s = 0, ph = 0;
        for (int ch = 0; ch < NCH; ch++) {
            const uint32_t fullb  = sb + 512 + s * 16;
            const uint32_t emptyb = fullb + 8;
            MBAR_WAIT(fullb, ph);
            const uint32_t stg = sb + STG(s);

#pragma unroll
            for (int kk = 0; kk < 4; kk++) {
                uint32_t a0f[4], a1f[4], b0f[4][4], b1f[4][4];
                const int cA = kk * 2 + cAoff;
                const int cB = kk * 2 + cBoff;
                uint32_t ad = stg + SW16(rowA, cA);
                ldsm4(a0f, ad);
                ldsm4(a1f, ad + AB);
#pragma unroll
                for (int j = 0; j < 4; j++) {
                    uint32_t bd = stg + WOFF + SW16(16 * j + rowBb, cB);
                    ldsm4(b0f[j], bd);
                    ldsm4(b1f[j], bd + WB);
                }
                if (kk == 3) MBAR_ARRIVE(emptyb);
#pragma unroll
                for (int ng = 0; ng < 8; ng++)
                    mma16816(acc0[ng], a0f, &b0f[ng >> 1][(ng & 1) * 2]);
#pragma unroll
                for (int ng = 0; ng < 8; ng++)
                    mma16816(acc0[ng], a1f, &b0f[ng >> 1][(ng & 1) * 2]);
#pragma unroll
                for (int ng = 0; ng < 8; ng++)
                    mma16816(acc1[ng], a0f, &b1f[ng >> 1][(ng & 1) * 2]);
            }
            if (++s == NSTG) { s = 0; ph ^= 1; }
        }

        asm volatile("bar.sync 1, 256;" ::: "memory");

#pragma unroll
        for (int ng = 0; ng < 8; ng++) {
            int row = m0 + (lane >> 2);
            int col = ng * 8 + 2 * (lane & 3);
            lg[row * LGS + col]           = acc0[ng][0] + S * acc1[ng][0];
            lg[row * LGS + col + 1]       = acc0[ng][1] + S * acc1[ng][1];
            lg[(row + 8) * LGS + col]     = acc0[ng][2] + S * acc1[ng][2];
            lg[(row + 8) * LGS + col + 1] = acc0[ng][3] + S * acc1[ng][3];
        }
    } else {
        // ---- LIGHT: n16 col-strip (wid-4), rows 64..111 (3 quanta = 18 MMAs/kk) ----
        const int n0 = (wid - 4) * 16;     // expert col base

        float acc0[3][2][4], acc1[3][2][4];
#pragma unroll
        for (int t = 0; t < 3; t++)
#pragma unroll
            for (int u = 0; u < 2; u++)
#pragma unroll
                for (int q = 0; q < 4; q++) { acc0[t][u][q] = 0.f; acc1[t][u][q] = 0.f; }

        const int rowAb = 64 + (lane & 15);
        const int cAoff = lane >> 4;
        const int rowB  = n0 + (lane & 7) + ((lane >> 4) << 3);
        const int cBoff = (lane >> 3) & 1;

        int s = 0, ph = 0;
        for (int ch = 0; ch < NCH; ch++) {
            const uint32_t fullb  = sb + 512 + s * 16;
            const uint32_t emptyb = fullb + 8;
            MBAR_WAIT(fullb, ph);
            const uint32_t stg = sb + STG(s);

#pragma unroll
            for (int kk = 0; kk < 4; kk++) {
                uint32_t a0f[3][4], a1f[3][4], b0f[4], b1f[4];
                const int cA = kk * 2 + cAoff;
                const int cB = kk * 2 + cBoff;
#pragma unroll
                for (int t = 0; t < 3; t++) {
                    uint32_t ad = stg + SW16(rowAb + 16 * t, cA);
                    ldsm4(a0f[t], ad);
                    ldsm4(a1f[t], ad + AB);
                }
                {
                    uint32_t bd = stg + WOFF + SW16(rowB, cB);
                    ldsm4(b0f, bd);
                    ldsm4(b1f, bd + WB);
                }
                if (kk == 3) MBAR_ARRIVE(emptyb);
                // pass-major, acc reuse distance 6
#pragma unroll
                for (int t = 0; t < 3; t++)
#pragma unroll
                    for (int u = 0; u < 2; u++)
                        mma16816(acc0[t][u], a0f[t], &b0f[u * 2]);
#pragma unroll
                for (int t = 0; t < 3; t++)
#pragma unroll
                    for (int u = 0; u < 2; u++)
                        mma16816(acc0[t][u], a1f[t], &b0f[u * 2]);
#pragma unroll
                for (int t = 0; t < 3; t++)
#pragma unroll
                    for (int u = 0; u < 2; u++)
                        mma16816(acc1[t][u], a0f[t], &b1f[u * 2]);
            }
            if (++s == NSTG) { s = 0; ph ^= 1; }
        }

        asm volatile("bar.sync 1, 256;" ::: "memory");

#pragma unroll
        for (int t = 0; t < 3; t++) {
#pragma unroll
            for (int u = 0; u < 2; u++) {
                int row = 64 + 16 * t + (lane >> 2);
                int col = n0 + u * 8 + 2 * (lane & 3);
                lg[row * LGS + col]           = acc0[t][u][0] + S * acc1[t][u][0];
                lg[row * LGS + col + 1]       = acc0[t][u][1] + S * acc1[t][u][1];
                lg[(row + 8) * LGS + col]     = acc0[t][u][2] + S * acc1[t][u][2];
                lg[(row + 8) * LGS + col + 1] = acc0[t][u][3] + S * acc1[t][u][3];
            }
        }
    }

    asm volatile("bar.sync 1, 256;" ::: "memory");

    // ---- top-2 + softmax, one thread per token ----
    if (tid < M_CTA && tok0 + tid < n_tokens) {
        const float* row = &lg[tid * LGS];
        const float* bs  = reinterpret_cast<const float*>(smem);
        float v1 = -3.402823466e+38f, v2 = -3.402823466e+38f;
        int i1 = 0, i2 = 0;
#pragma unroll
        for (int e = 0; e < NEXP; e++) {
            float v = row[e] + bs[e];
            if (v > v1)      { v2 = v1; i2 = i1; v1 = v; i1 = e; }
            else if (v > v2) { v2 = v;  i2 = e; }
        }
        float e2  = expf(v2 - v1);
        float inv = 1.0f / (1.0f + e2);
        const int g = tok0 + tid;
        out[2 * g + 0] = inv;
        out[2 * g + 1] = e2 * inv;
        out[2 * n_tokens + 2 * g + 0] = (float)i1;
        out[2 * n_tokens + 2 * g + 1] = (float)i2;
    }
}

// ---------------- launch ----------------
extern "C" void kernel_launch(void* const* d_in, const int* in_sizes, int n_in,
                              void* d_out, int out_size)
{
    const float* x = (const float*)d_in[0];
    const float* W = (const float*)d_in[1];
    const float* b = (const float*)d_in[2];
    float* out = (float*)d_out;

    const int n_tokens = in_sizes[0] / D_DIM;            // 16384
    const int grid = (n_tokens + M_CTA - 1) / M_CTA;     // 147

    cudaFuncSetAttribute(router_main, cudaFuncAttributeMaxDynamicSharedMemorySize, SMEM_TOTAL);

    wconv<<<NEXP * D_DIM / 256, 256>>>(W);
    router_main<<<grid, NTHREADS, SMEM_TOTAL>>>(x, b, out, n_tokens);
}

// round 16
// speedup vs baseline: 1.4613x; 1.4613x over previous
#include <cuda_runtime.h>
#include <cuda_fp16.h>
#include <cstdint>

// ============================================================
// TopKRouter, warp-specialized HMMA fp16 2-split pipeline v8:
//   logits = x @ W^T + b ; top-2 ; softmax(top2)
// R7 base (best 72.2us) + COALESCED producer mapping:
//   old: thread-owns-row -> 32 L1 wavefronts per warp-LDG
//   new: thread-owns-column -> 4 wavefronts per warp-LDG (8x)
// M_CTA=128, 384 thr: w0-7 consumers (m32n32), w8-11 producers.
// ============================================================

#define D_DIM  2048
#define NEXP   64
#define M_CTA  128
#define NCH    32
#define NSTG   4
#define NTHREADS 384

#define AB       16384
#define WB       8192
#define WOFF     32768
#define STGSZ    49152
#define STG(s)   (1024 + (s) * STGSZ)
#define SMEM_TOTAL (1024 + NSTG * STGSZ)   // 197632
#define LG_OFF   1024
#define LGS      65
#define SW16(row, c) ((row) * 128 + ((((c) ^ ((row) & 7))) << 4))

__device__ __align__(16) __half w0g[NEXP * D_DIM];
__device__ __align__(16) __half w1g[NEXP * D_DIM];

__global__ void wconv(const float* __restrict__ W) {
    int i = blockIdx.x * blockDim.x + threadIdx.x;
    float w = W[i];
    __half h0 = __float2half_rn(w);
    float  r  = w - __half2float(h0);
    w0g[i] = h0;
    w1g[i] = __float2half_rn(r * 2048.0f);
}

// ---------------- asm helpers ----------------
__device__ __forceinline__ uint32_t smem_u32(const void* p) {
    uint32_t a;
    asm("{ .reg .u64 t; cvta.to.shared.u64 t, %1; cvt.u32.u64 %0, t; }"
        : "=r"(a) : "l"(p));
    return a;
}
__device__ __forceinline__ void ldsm4(uint32_t* r, uint32_t addr) {
    asm volatile("ldmatrix.sync.aligned.m8n8.x4.shared.b16 {%0,%1,%2,%3}, [%4];"
                 : "=r"(r[0]), "=r"(r[1]), "=r"(r[2]), "=r"(r[3]) : "r"(addr));
}
__device__ __forceinline__ void mma16816(float* d, const uint32_t* a, const uint32_t* b) {
    asm volatile("mma.sync.aligned.m16n8k16.row.col.f32.f16.f16.f32 "
                 "{%0,%1,%2,%3}, {%4,%5,%6,%7}, {%8,%9}, {%0,%1,%2,%3};"
                 : "+f"(d[0]), "+f"(d[1]), "+f"(d[2]), "+f"(d[3])
                 : "r"(a[0]), "r"(a[1]), "r"(a[2]), "r"(a[3]), "r"(b[0]), "r"(b[1]));
}
__device__ __forceinline__ void cp16(uint32_t saddr, const void* gaddr) {
    asm volatile("cp.async.cg.shared.global [%0], [%1], 16;" :: "r"(saddr), "l"(gaddr));
}
#define MBAR_INIT(a, c) \
    asm volatile("mbarrier.init.shared.b64 [%0], %1;" :: "r"(a), "r"(c) : "memory")
#define MBAR_ARRIVE(a) \
    asm volatile("mbarrier.arrive.release.cta.shared::cta.b64 _, [%0];" :: "r"(a) : "memory")
// .noinc is load-bearing (default raises pend-count -> deadlock)
#define CP_MBAR_ARRIVE(a) \
    asm volatile("cp.async.mbarrier.arrive.noinc.shared.b64 [%0];" :: "r"(a) : "memory")
#define MBAR_WAIT(addr, ph) do { \
    asm volatile("{\n\t.reg .pred P;\n\tWLP_%=:\n\t" \
        "mbarrier.try_wait.parity.acquire.cta.shared::cta.b64 P, [%0], %1, 0x989680;\n\t" \
        "@!P bra WLP_%=;\n\t}" :: "r"(addr), "r"(ph) : "memory"); \
} while (0)
#define STS64(addr, u0, u1) \
    asm volatile("st.shared.v2.b32 [%0], {%1,%2};" :: "r"(addr), "r"(u0), "r"(u1) : "memory")

__device__ __forceinline__ uint32_t cvt2(float u, float v, uint32_t& h1) {
    __half2 a = __float22half2_rn(make_float2(u, v));
    float2 f  = __half22float2(a);
    __half2 r = __float22half2_rn(make_float2(u - f.x, v - f.y));
    h1 = *reinterpret_cast<uint32_t*>(&r);
    return *reinterpret_cast<uint32_t*>(&a);
}

// ---------------- main kernel ----------------
__global__ __launch_bounds__(NTHREADS)
void router_main(const float* __restrict__ x, const float* __restrict__ b,
                 float* __restrict__ out, int n_tokens)
{
    extern __shared__ __align__(1024) char smem[];
    const uint32_t sb = smem_u32(smem);
    const int tid  = threadIdx.x;
    const int lane = tid & 31;
    const int tok0 = blockIdx.x * M_CTA;

    if (tid == 0) {
#pragma unroll
        for (int s = 0; s < NSTG; s++) {
            MBAR_INIT(sb + 512 + s * 16, 256);      // 128 STS-arr + 128 cp-arr
            MBAR_INIT(sb + 512 + s * 16 + 8, 256);  // 256 consumer arrivals
        }
    }
    if (tid < NEXP) reinterpret_cast<float*>(smem)[tid] = b[tid];
    __syncthreads();

    if (tid >= 256) {
        // ====== PRODUCER (warps 8-11) — COALESCED column-owner mapping ======
        const int pt = tid - 256;          // 0..127
        const int c  = pt & 15;            // f4 column within 64-f32 chunk row
        const int r0 = pt >> 4;            // base row 0..7; rows r0 + 8i
        // lanes of one warp: 2 rows x 16 consecutive f4 -> 4 lines / warp-LDG
        const float4* xp = reinterpret_cast<const float4*>(x)
                           + (size_t)(tok0 + r0) * (D_DIM / 4) + c;
        // smem: 16B slot col = c>>1, 8B half = c&1
        uint32_t asw[16];
#pragma unroll
        for (int i = 0; i < 16; i++)
            asw[i] = SW16(r0 + 8 * i, (c >> 1)) + (c & 1) * 8;

        // W cp mapping: L = pt + 128*i -> split, row, col (fully coalesced)
        const char* wg0 = reinterpret_cast<const char*>(w0g);
        const char* wg1 = reinterpret_cast<const char*>(w1g);

        float4 xv[16];
#pragma unroll
        for (int i = 0; i < 16; i++) xv[i] = xp[(size_t)i * 8 * (D_DIM / 4)];

        int s = 0, ph = 1;
        for (int ch = 0; ch < NCH; ch++) {
            const uint32_t fullb  = sb + 512 + s * 16;
            const uint32_t emptyb = fullb + 8;
            MBAR_WAIT(emptyb, ph);
            const uint32_t stg = sb + STG(s);

            // W chunk: 1024 cp16 linear (8 per thread), coalesced
#pragma unroll
            for (int i = 0; i < 8; i++) {
                const int L   = pt + 128 * i;
                const int sp  = L >> 9;          // 0: w0, 1: w1
                const int wr  = (L >> 3) & 63;
                const int wc  = L & 7;
                const char* src = (sp ? wg1 : wg0)
                                  + (size_t)wr * (D_DIM * 2) + ch * 128 + wc * 16;
                cp16(stg + WOFF + sp * WB + SW16(wr, wc), src);
            }

            // x split: 16 rows-owned f4 -> STS64 h0 + STS64 h1 each
#pragma unroll
            for (int i = 0; i < 16; i++) {
                float4 v = xv[i];
                uint32_t h1lo, h1hi;
                uint32_t h0lo = cvt2(v.x, v.y, h1lo);
                uint32_t h0hi = cvt2(v.z, v.w, h1hi);
                STS64(stg + asw[i], h0lo, h0hi);
                STS64(stg + AB + asw[i], h1lo, h1hi);
            }
            CP_MBAR_ARRIVE(fullb);
            MBAR_ARRIVE(fullb);

            if (ch + 1 < NCH) {
#pragma unroll
                for (int i = 0; i < 16; i++)
                    xv[i] = xp[(size_t)i * 8 * (D_DIM / 4) + (ch + 1) * 16];
            }
            if (++s == NSTG) { s = 0; ph ^= 1; }
        }
        return;
    }

    // ================= CONSUMER (warps 0-7, 32x32 tiles — R7 verbatim) =================
    const int wid = tid >> 5;
    const int m0  = (wid & 3) * 32;
    const int n0  = (wid >> 2) * 32;

    float acc0[2][4][4], acc1[2][4][4];
#pragma unroll
    for (int mi = 0; mi < 2; mi++)
#pragma unroll
        for (int ng = 0; ng < 4; ng++)
#pragma unroll
            for (int q = 0; q < 4; q++) { acc0[mi][ng][q] = 0.f; acc1[mi][ng][q] = 0.f; }

    const int rowA  = m0 + (lane & 15);
    const int cAoff = lane >> 4;
    const int rowB  = n0 + (lane & 7) + ((lane >> 4) << 3);
    const int cBoff = (lane >> 3) & 1;

    int s = 0, ph = 0;
    for (int ch = 0; ch < NCH; ch++) {
        const uint32_t fullb  = sb + 512 + s * 16;
        const uint32_t emptyb = fullb + 8;
        MBAR_WAIT(fullb, ph);
        const uint32_t stg = sb + STG(s);

#pragma unroll
        for (int kk = 0; kk < 4; kk++) {
            uint32_t a0f[2][4], a1f[2][4], b0f[2][4], b1f[2][4];
            const int cA = kk * 2 + cAoff;
            const int cB = kk * 2 + cBoff;
#pragma unroll
            for (int mi = 0; mi < 2; mi++) {
                uint32_t ad = stg + SW16(rowA + mi * 16, cA);
                ldsm4(a0f[mi], ad);
                ldsm4(a1f[mi], ad + AB);
            }
#pragma unroll
            for (int ni2 = 0; ni2 < 2; ni2++) {
                uint32_t bd = stg + WOFF + SW16(rowB + ni2 * 16, cB);
                ldsm4(b0f[ni2], bd);
                ldsm4(b1f[ni2], bd + WB);
            }
            // pass-major MMA order: acc reuse distance 8
#pragma unroll
            for (int mi = 0; mi < 2; mi++)
#pragma unroll
                for (int ng = 0; ng < 4; ng++)
                    mma16816(acc0[mi][ng], a0f[mi], &b0f[ng >> 1][(ng & 1) * 2]);
#pragma unroll
            for (int mi = 0; mi < 2; mi++)
#pragma unroll
                for (int ng = 0; ng < 4; ng++)
                    mma16816(acc0[mi][ng], a1f[mi], &b0f[ng >> 1][(ng & 1) * 2]);
#pragma unroll
            for (int mi = 0; mi < 2; mi++)
#pragma unroll
                for (int ng = 0; ng < 4; ng++)
                    mma16816(acc1[mi][ng], a0f[mi], &b1f[ng >> 1][(ng & 1) * 2]);
        }
        MBAR_ARRIVE(emptyb);
        if (++s == NSTG) { s = 0; ph ^= 1; }
    }

    // consumers must finish reading stage 0 before logits overwrite it
    asm volatile("bar.sync 1, 256;" ::: "memory");

    // ---- epilogue: combine splits -> logits smem ----
    float* lg = reinterpret_cast<float*>(smem + LG_OFF);
    const float S = 4.8828125e-4f;  // 2^-11
#pragma unroll
    for (int mi = 0; mi < 2; mi++) {
#pragma unroll
        for (int ng = 0; ng < 4; ng++) {
            int row = m0 + mi * 16 + (lane >> 2);
            int col = n0 + ng * 8 + 2 * (lane & 3);
            lg[row * LGS + col]           = acc0[mi][ng][0] + S * acc1[mi][ng][0];
            lg[row * LGS + col + 1]       = acc0[mi][ng][1] + S * acc1[mi][ng][1];
            lg[(row + 8) * LGS + col]     = acc0[mi][ng][2] + S * acc1[mi][ng][2];
            lg[(row + 8) * LGS + col + 1] = acc0[mi][ng][3] + S * acc1[mi][ng][3];
        }
    }
    asm volatile("bar.sync 1, 256;" ::: "memory");

    // ---- top-2 + softmax, one thread per token ----
    if (tid < M_CTA) {
        const float* row = &lg[tid * LGS];
        const float* bs  = reinterpret_cast<const float*>(smem);
        float v1 = -3.402823466e+38f, v2 = -3.402823466e+38f;
        int i1 = 0, i2 = 0;
#pragma unroll
        for (int e = 0; e < NEXP; e++) {
            float v = row[e] + bs[e];
            if (v > v1)      { v2 = v1; i2 = i1; v1 = v; i1 = e; }
            else if (v > v2) { v2 = v;  i2 = e; }
        }
        float e2  = expf(v2 - v1);
        float inv = 1.0f / (1.0f + e2);
        const int g = tok0 + tid;
        out[2 * g + 0] = inv;
        out[2 * g + 1] = e2 * inv;
        out[2 * n_tokens + 2 * g + 0] = (float)i1;
        out[2 * n_tokens + 2 * g + 1] = (float)i2;
    }
}

// ---------------- launch ----------------
extern "C" void kernel_launch(void* const* d_in, const int* in_sizes, int n_in,
                              void* d_out, int out_size)
{
    const float* x = (const float*)d_in[0];
    const float* W = (const float*)d_in[1];
    const float* b = (const float*)d_in[2];
    float* out = (float*)d_out;

    const int n_tokens = in_sizes[0] / D_DIM;   // 16384
    const int grid = n_tokens / M_CTA;          // 128

    cudaFuncSetAttribute(router_main, cudaFuncAttributeMaxDynamicSharedMemorySize, SMEM_TOTAL);

    wconv<<<NEXP * D_DIM / 256, 256>>>(W);
    router_main<<<grid, NTHREADS, SMEM_TOTAL>>>(x, b, out, n_tokens);
}

// round 17
// speedup vs baseline: 1.5296x; 1.0467x over previous
#include <cuda_runtime.h>
#include <cuda_fp16.h>
#include <cstdint>

// ============================================================
// TopKRouter, warp-specialized HMMA fp16 2-split pipeline v9:
//   logits = x @ W^T + b ; top-2 ; softmax(top2)
// R16 base (53.8us) + FAT CONSUMER TILES:
//   4 consumer warps m32n64 (was 8x m32n32) -> ldsm bytes
//   96KB/chunk vs 128KB (-25% L1 wavefronts), and 256 threads
//   -> 255-reg ceiling so the 200-reg consumer fits, no spills.
// 256 thr: w0-3 consumers, w4-7 producers (R16 coalesced code).
// ============================================================

#define D_DIM  2048
#define NEXP   64
#define M_CTA  128
#define NCH    32
#define NSTG   4
#define NTHREADS 256

#define AB       16384
#define WB       8192
#define WOFF     32768
#define STGSZ    49152
#define STG(s)   (1024 + (s) * STGSZ)
#define SMEM_TOTAL (1024 + NSTG * STGSZ)   // 197632
#define LG_OFF   1024
#define LGS      65
#define SW16(row, c) ((row) * 128 + ((((c) ^ ((row) & 7))) << 4))

__device__ __align__(16) __half w0g[NEXP * D_DIM];
__device__ __align__(16) __half w1g[NEXP * D_DIM];

__global__ void wconv(const float* __restrict__ W) {
    int i = blockIdx.x * blockDim.x + threadIdx.x;
    float w = W[i];
    __half h0 = __float2half_rn(w);
    float  r  = w - __half2float(h0);
    w0g[i] = h0;
    w1g[i] = __float2half_rn(r * 2048.0f);
}

// ---------------- asm helpers ----------------
__device__ __forceinline__ uint32_t smem_u32(const void* p) {
    uint32_t a;
    asm("{ .reg .u64 t; cvta.to.shared.u64 t, %1; cvt.u32.u64 %0, t; }"
        : "=r"(a) : "l"(p));
    return a;
}
__device__ __forceinline__ void ldsm4(uint32_t* r, uint32_t addr) {
    asm volatile("ldmatrix.sync.aligned.m8n8.x4.shared.b16 {%0,%1,%2,%3}, [%4];"
                 : "=r"(r[0]), "=r"(r[1]), "=r"(r[2]), "=r"(r[3]) : "r"(addr));
}
__device__ __forceinline__ void mma16816(float* d, const uint32_t* a, const uint32_t* b) {
    asm volatile("mma.sync.aligned.m16n8k16.row.col.f32.f16.f16.f32 "
                 "{%0,%1,%2,%3}, {%4,%5,%6,%7}, {%8,%9}, {%0,%1,%2,%3};"
                 : "+f"(d[0]), "+f"(d[1]), "+f"(d[2]), "+f"(d[3])
                 : "r"(a[0]), "r"(a[1]), "r"(a[2]), "r"(a[3]), "r"(b[0]), "r"(b[1]));
}
__device__ __forceinline__ void cp16(uint32_t saddr, const void* gaddr) {
    asm volatile("cp.async.cg.shared.global [%0], [%1], 16;" :: "r"(saddr), "l"(gaddr));
}
#define MBAR_INIT(a, c) \
    asm volatile("mbarrier.init.shared.b64 [%0], %1;" :: "r"(a), "r"(c) : "memory")
#define MBAR_ARRIVE(a) \
    asm volatile("mbarrier.arrive.release.cta.shared::cta.b64 _, [%0];" :: "r"(a) : "memory")
// .noinc is load-bearing (default raises pend-count -> deadlock)
#define CP_MBAR_ARRIVE(a) \
    asm volatile("cp.async.mbarrier.arrive.noinc.shared.b64 [%0];" :: "r"(a) : "memory")
#define MBAR_WAIT(addr, ph) do { \
    asm volatile("{\n\t.reg .pred P;\n\tWLP_%=:\n\t" \
        "mbarrier.try_wait.parity.acquire.cta.shared::cta.b64 P, [%0], %1, 0x989680;\n\t" \
        "@!P bra WLP_%=;\n\t}" :: "r"(addr), "r"(ph) : "memory"); \
} while (0)
#define STS64(addr, u0, u1) \
    asm volatile("st.shared.v2.b32 [%0], {%1,%2};" :: "r"(addr), "r"(u0), "r"(u1) : "memory")

__device__ __forceinline__ uint32_t cvt2(float u, float v, uint32_t& h1) {
    __half2 a = __float22half2_rn(make_float2(u, v));
    float2 f  = __half22float2(a);
    __half2 r = __float22half2_rn(make_float2(u - f.x, v - f.y));
    h1 = *reinterpret_cast<uint32_t*>(&r);
    return *reinterpret_cast<uint32_t*>(&a);
}

// ---------------- main kernel ----------------
__global__ __launch_bounds__(NTHREADS)
void router_main(const float* __restrict__ x, const float* __restrict__ b,
                 float* __restrict__ out, int n_tokens)
{
    extern __shared__ __align__(1024) char smem[];
    const uint32_t sb = smem_u32(smem);
    const int tid  = threadIdx.x;
    const int lane = tid & 31;
    const int tok0 = blockIdx.x * M_CTA;

    if (tid == 0) {
#pragma unroll
        for (int s = 0; s < NSTG; s++) {
            MBAR_INIT(sb + 512 + s * 16, 256);      // 128 STS-arr + 128 cp-arr
            MBAR_INIT(sb + 512 + s * 16 + 8, 128);  // 128 consumer arrivals
        }
    }
    if (tid < NEXP) reinterpret_cast<float*>(smem)[tid] = b[tid];
    __syncthreads();

    if (tid >= 128) {
        // ====== PRODUCER (warps 4-7) — R16 coalesced column-owner mapping ======
        const int pt = tid - 128;          // 0..127
        const int c  = pt & 15;            // f4 column within 64-f32 chunk row
        const int r0 = pt >> 4;            // base row 0..7; rows r0 + 8i
        const float4* xp = reinterpret_cast<const float4*>(x)
                           + (size_t)(tok0 + r0) * (D_DIM / 4) + c;
        uint32_t asw[16];
#pragma unroll
        for (int i = 0; i < 16; i++)
            asw[i] = SW16(r0 + 8 * i, (c >> 1)) + (c & 1) * 8;

        const char* wg0 = reinterpret_cast<const char*>(w0g);
        const char* wg1 = reinterpret_cast<const char*>(w1g);

        float4 xv[16];
#pragma unroll
        for (int i = 0; i < 16; i++) xv[i] = xp[(size_t)i * 8 * (D_DIM / 4)];

        int s = 0, ph = 1;
        for (int ch = 0; ch < NCH; ch++) {
            const uint32_t fullb  = sb + 512 + s * 16;
            const uint32_t emptyb = fullb + 8;
            MBAR_WAIT(emptyb, ph);
            const uint32_t stg = sb + STG(s);

            // W chunk: 1024 cp16 linear (8 per thread), coalesced
#pragma unroll
            for (int i = 0; i < 8; i++) {
                const int L   = pt + 128 * i;
                const int sp  = L >> 9;          // 0: w0, 1: w1
                const int wr  = (L >> 3) & 63;
                const int wc  = L & 7;
                const char* src = (sp ? wg1 : wg0)
                                  + (size_t)wr * (D_DIM * 2) + ch * 128 + wc * 16;
                cp16(stg + WOFF + sp * WB + SW16(wr, wc), src);
            }

            // x split: 16 rows-owned f4 -> STS64 h0 + STS64 h1 each
#pragma unroll
            for (int i = 0; i < 16; i++) {
                float4 v = xv[i];
                uint32_t h1lo, h1hi;
                uint32_t h0lo = cvt2(v.x, v.y, h1lo);
                uint32_t h0hi = cvt2(v.z, v.w, h1hi);
                STS64(stg + asw[i], h0lo, h0hi);
                STS64(stg + AB + asw[i], h1lo, h1hi);
            }
            CP_MBAR_ARRIVE(fullb);
            MBAR_ARRIVE(fullb);

            if (ch + 1 < NCH) {
#pragma unroll
                for (int i = 0; i < 16; i++)
                    xv[i] = xp[(size_t)i * 8 * (D_DIM / 4) + (ch + 1) * 16];
            }
            if (++s == NSTG) { s = 0; ph ^= 1; }
        }
        return;
    }

    // ================= CONSUMER (warps 0-3): m32n64 each =================
    const int wid = tid >> 5;
    const int m0  = wid * 32;

    float acc0[2][8][4], acc1[2][8][4];
#pragma unroll
    for (int mi = 0; mi < 2; mi++)
#pragma unroll
        for (int ng = 0; ng < 8; ng++)
#pragma unroll
            for (int q = 0; q < 4; q++) { acc0[mi][ng][q] = 0.f; acc1[mi][ng][q] = 0.f; }

    const int rowA  = m0 + (lane & 15);
    const int cAoff = lane >> 4;
    const int rowBb = (lane & 7) + ((lane >> 4) << 3);
    const int cBoff = (lane >> 3) & 1;

    int s = 0, ph = 0;
    for (int ch = 0; ch < NCH; ch++) {
        const uint32_t fullb  = sb + 512 + s * 16;
        const uint32_t emptyb = fullb + 8;
        MBAR_WAIT(fullb, ph);
        const uint32_t stg = sb + STG(s);

#pragma unroll
        for (int kk = 0; kk < 4; kk++) {
            uint32_t a0f[2][4], a1f[2][4], b0f[4][4], b1f[4][4];
            const int cA = kk * 2 + cAoff;
            const int cB = kk * 2 + cBoff;
#pragma unroll
            for (int mi = 0; mi < 2; mi++) {
                uint32_t ad = stg + SW16(rowA + mi * 16, cA);
                ldsm4(a0f[mi], ad);
                ldsm4(a1f[mi], ad + AB);
            }
#pragma unroll
            for (int j = 0; j < 4; j++) {
                uint32_t bd = stg + WOFF + SW16(16 * j + rowBb, cB);
                ldsm4(b0f[j], bd);
                ldsm4(b1f[j], bd + WB);
            }
            if (kk == 3) MBAR_ARRIVE(emptyb);
            // pass-major MMA order: acc reuse distance 16 -> no RAW stalls
#pragma unroll
            for (int mi = 0; mi < 2; mi++)
#pragma unroll
                for (int ng = 0; ng < 8; ng++)
                    mma16816(acc0[mi][ng], a0f[mi], &b0f[ng >> 1][(ng & 1) * 2]);
#pragma unroll
            for (int mi = 0; mi < 2; mi++)
#pragma unroll
                for (int ng = 0; ng < 8; ng++)
                    mma16816(acc0[mi][ng], a1f[mi], &b0f[ng >> 1][(ng & 1) * 2]);
#pragma unroll
            for (int mi = 0; mi < 2; mi++)
#pragma unroll
                for (int ng = 0; ng < 8; ng++)
                    mma16816(acc1[mi][ng], a0f[mi], &b1f[ng >> 1][(ng & 1) * 2]);
        }
        if (++s == NSTG) { s = 0; ph ^= 1; }
    }

    // consumers must finish reading stage 0 before logits overwrite it
    asm volatile("bar.sync 1, 128;" ::: "memory");

    // ---- epilogue: combine splits -> logits smem ----
    float* lg = reinterpret_cast<float*>(smem + LG_OFF);
    const float S = 4.8828125e-4f;  // 2^-11
#pragma unroll
    for (int mi = 0; mi < 2; mi++) {
#pragma unroll
        for (int ng = 0; ng < 8; ng++) {
            int row = m0 + mi * 16 + (lane >> 2);
            int col = ng * 8 + 2 * (lane & 3);
            lg[row * LGS + col]           = acc0[mi][ng][0] + S * acc1[mi][ng][0];
            lg[row * LGS + col + 1]       = acc0[mi][ng][1] + S * acc1[mi][ng][1];
            lg[(row + 8) * LGS + col]     = acc0[mi][ng][2] + S * acc1[mi][ng][2];
            lg[(row + 8) * LGS + col + 1] = acc0[mi][ng][3] + S * acc1[mi][ng][3];
        }
    }
    asm volatile("bar.sync 1, 128;" ::: "memory");

    // ---- top-2 + softmax, one thread per token (128 consumers) ----
    {
        const float* row = &lg[tid * LGS];
        const float* bs  = reinterpret_cast<const float*>(smem);
        float v1 = -3.402823466e+38f, v2 = -3.402823466e+38f;
        int i1 = 0, i2 = 0;
#pragma unroll
        for (int e = 0; e < NEXP; e++) {
            float v = row[e] + bs[e];
            if (v > v1)      { v2 = v1; i2 = i1; v1 = v; i1 = e; }
            else if (v > v2) { v2 = v;  i2 = e; }
        }
        float e2  = expf(v2 - v1);
        float inv = 1.0f / (1.0f + e2);
        const int g = tok0 + tid;
        out[2 * g + 0] = inv;
        out[2 * g + 1] = e2 * inv;
        out[2 * n_tokens + 2 * g + 0] = (float)i1;
        out[2 * n_tokens + 2 * g + 1] = (float)i2;
    }
}

// ---------------- launch ----------------
extern "C" void kernel_launch(void* const* d_in, const int* in_sizes, int n_in,
                              void* d_out, int out_size)
{
    const float* x = (const float*)d_in[0];
    const float* W = (const float*)d_in[1];
    const float* b = (const float*)d_in[2];
    float* out = (float*)d_out;

    const int n_tokens = in_sizes[0] / D_DIM;   // 16384
    const int grid = n_tokens / M_CTA;          // 128

    cudaFuncSetAttribute(router_main, cudaFuncAttributeMaxDynamicSharedMemorySize, SMEM_TOTAL);

    wconv<<<NEXP * D_DIM / 256, 256>>>(W);
    router_main<<<grid, NTHREADS, SMEM_TOTAL>>>(x, b, out, n_tokens);
}